// round 13
// baseline (speedup 1.0000x reference)
#include <cuda_runtime.h>

// ---------------------------------------------------------------------------
// GCN 2-layer + mean-pool + FC for GB300 (sm_103a)
//   h1 = x @ W1                                  (f32x2-packed SGEMM)
//   o1 = b1 + D^-1/2 (A+I) D^-1/2 h1             (self-loop init + edge red.v4)
//   h2 = relu(o1) @ W2                           (same SGEMM, relu fused on load)
//   o2 = b2 + D^-1/2 (A+I) D^-1/2 h2
//   pool[g] = sum relu(o2[i]) over batch, cnt[g]
//   out[g]  = dot(pool[g], Wfc)/max(cnt,1) + bfc
// ---------------------------------------------------------------------------

#define N_MAX   100000
#define HID     64
#define GRAPHS  256

// Scratch (static device globals: no allocation, graph-capture safe)
__device__ float g_h   [(size_t)N_MAX * HID];   // h1, then h2
__device__ float g_o   [(size_t)N_MAX * HID];   // conv1 out, then conv2 out
__device__ float g_deg [N_MAX];
__device__ float g_dinv[N_MAX];
__device__ float g_pool[GRAPHS * HID];
__device__ float g_cnt [GRAPHS];

// ---------------- packed f32x2 helpers (FFMA2: 2x fp32 FMA throughput) ------
__device__ __forceinline__ unsigned long long pack2(float x, float y) {
    unsigned long long r;
    asm("mov.b64 %0, {%1, %2};" : "=l"(r) : "f"(x), "f"(y));
    return r;
}
__device__ __forceinline__ void unpack2(unsigned long long v, float& x, float& y) {
    asm("mov.b64 {%0, %1}, %2;" : "=f"(x), "=f"(y) : "l"(v));
}
__device__ __forceinline__ void ffma2(unsigned long long& d,
                                      unsigned long long a, unsigned long long b) {
    asm("fma.rn.f32x2 %0, %1, %2, %3;" : "=l"(d) : "l"(a), "l"(b), "l"(d));
}

// ---------------- init: deg=1 (self loop), pool=0, cnt=0 --------------------
__global__ void k_init(int n) {
    int t = blockIdx.x * blockDim.x + threadIdx.x;
    if (t < n)             g_deg[t]  = 1.0f;
    if (t < GRAPHS * HID)  g_pool[t] = 0.0f;
    if (t < GRAPHS)        g_cnt[t]  = 0.0f;
}

// ---------------- degree accumulation over dst -------------------------------
__global__ void k_deg(const int* __restrict__ dst, int E) {
    int e = blockIdx.x * blockDim.x + threadIdx.x;
    if (e < E) atomicAdd(&g_deg[dst[e]], 1.0f);
}

__global__ void k_dinv(int n) {
    int i = blockIdx.x * blockDim.x + threadIdx.x;
    if (i < n) g_dinv[i] = rsqrtf(g_deg[i]);
}

// ---------------- SGEMM: C(g_h) = [relu?](A) @ W,  N fixed = 64 -------------
// BM=128, BN=64, BK=32; 256 threads; each thread computes 8 rows x 4 cols,
// accumulated as packed f32x2 pairs (FFMA2).
template<int K, bool RELU>
__global__ __launch_bounds__(256)
void k_gemm(const float* __restrict__ Ain, const float* __restrict__ W, int M) {
    const float* __restrict__ A = RELU ? (const float*)g_o : Ain;

    const int BM = 128, BK = 32;
    __shared__ float As[BK][BM + 4];   // +4 pad: conflict reduction, keeps 16B align
    __shared__ float Bs[BK][HID];

    int tid  = threadIdx.x;
    int ty   = tid >> 4;      // 0..15 -> 8-row group
    int tx   = tid & 15;      // 0..15 -> 4-col group
    int row0 = blockIdx.x * BM;

    unsigned long long acc[8][2];
#pragma unroll
    for (int i = 0; i < 8; i++) { acc[i][0] = 0ull; acc[i][1] = 0ull; }

    for (int k0 = 0; k0 < K; k0 += BK) {
        // A tile: 128x32 = 1024 float4, 4 per thread, stored transposed
#pragma unroll
        for (int i = 0; i < 4; i++) {
            int f  = tid + i * 256;          // 0..1023
            int r  = f >> 3;                 // tile row
            int c4 = f & 7;                  // float4 col
            int gr = row0 + r;
            float4 v = make_float4(0.f, 0.f, 0.f, 0.f);
            if (gr < M) v = *(const float4*)(A + (size_t)gr * K + k0 + c4 * 4);
            if (RELU) {
                v.x = fmaxf(v.x, 0.f); v.y = fmaxf(v.y, 0.f);
                v.z = fmaxf(v.z, 0.f); v.w = fmaxf(v.w, 0.f);
            }
            As[c4 * 4 + 0][r] = v.x; As[c4 * 4 + 1][r] = v.y;
            As[c4 * 4 + 2][r] = v.z; As[c4 * 4 + 3][r] = v.w;
        }
        // B tile: 32x64 = 512 float4, 2 per thread
#pragma unroll
        for (int i = 0; i < 2; i++) {
            int f  = tid + i * 256;          // 0..511
            int r  = f >> 4;                 // k row
            int c4 = f & 15;
            *(float4*)&Bs[r][c4 * 4] =
                *(const float4*)(W + (size_t)(k0 + r) * HID + c4 * 4);
        }
        __syncthreads();

#pragma unroll
        for (int kk = 0; kk < BK; kk++) {
            float4 b = *(const float4*)&Bs[kk][tx * 4];
            unsigned long long b0 = pack2(b.x, b.y);
            unsigned long long b1 = pack2(b.z, b.w);
            float a[8];
            *(float4*)&a[0] = *(const float4*)&As[kk][ty * 8];
            *(float4*)&a[4] = *(const float4*)&As[kk][ty * 8 + 4];
#pragma unroll
            for (int i = 0; i < 8; i++) {
                unsigned long long a2 = pack2(a[i], a[i]);
                ffma2(acc[i][0], a2, b0);
                ffma2(acc[i][1], a2, b1);
            }
        }
        __syncthreads();
    }

#pragma unroll
    for (int i = 0; i < 8; i++) {
        int gr = row0 + ty * 8 + i;
        if (gr < M) {
            float4 v;
            unpack2(acc[i][0], v.x, v.y);
            unpack2(acc[i][1], v.z, v.w);
            *(float4*)(g_h + (size_t)gr * HID + tx * 4) = v;
        }
    }
}

// ---------------- self-loop + bias init: g_o = bias + g_h * dinv^2 ----------
__global__ void k_self(const float* __restrict__ bias, int n) {
    int t = blockIdx.x * blockDim.x + threadIdx.x;
    int i = t >> 4;
    if (i >= n) return;
    int c = (t & 15) * 4;
    float di = g_dinv[i];
    float s  = di * di;
    float4 v  = *(const float4*)(g_h + (size_t)i * HID + c);
    float4 bb = *(const float4*)(bias + c);
    float4 o;
    o.x = bb.x + v.x * s; o.y = bb.y + v.y * s;
    o.z = bb.z + v.z * s; o.w = bb.w + v.w * s;
    *(float4*)(g_o + (size_t)i * HID + c) = o;
}

// ---------------- edge scatter: g_o[dst] += g_h[src] * dinv[s]*dinv[d] ------
// 16 threads per edge, float4 per thread, vector reduction (no return trip).
__global__ void k_edge(const int* __restrict__ src, const int* __restrict__ dst,
                       int E) {
    int t = blockIdx.x * blockDim.x + threadIdx.x;
    int e = t >> 4;
    if (e >= E) return;
    int c = (t & 15) * 4;
    int s = src[e];
    int d = dst[e];
    float nrm = g_dinv[s] * g_dinv[d];
    float4 v = *(const float4*)(g_h + (size_t)s * HID + c);
    float* p = g_o + (size_t)d * HID + c;
    asm volatile("red.global.add.v4.f32 [%0], {%1, %2, %3, %4};"
                 :: "l"(p), "f"(v.x * nrm), "f"(v.y * nrm),
                    "f"(v.z * nrm), "f"(v.w * nrm)
                 : "memory");
}

// ---------------- pooling: pool[batch[i]] += relu(g_o[i]); cnt[b] += 1 ------
__global__ void k_pool(const int* __restrict__ batch, int n) {
    int t = blockIdx.x * blockDim.x + threadIdx.x;
    int i = t >> 4;
    if (i >= n) return;
    int c = (t & 15) * 4;
    int b = batch[i];
    float4 v = *(const float4*)(g_o + (size_t)i * HID + c);
    v.x = fmaxf(v.x, 0.f); v.y = fmaxf(v.y, 0.f);
    v.z = fmaxf(v.z, 0.f); v.w = fmaxf(v.w, 0.f);
    float* p = g_pool + (size_t)b * HID + c;
    asm volatile("red.global.add.v4.f32 [%0], {%1, %2, %3, %4};"
                 :: "l"(p), "f"(v.x), "f"(v.y), "f"(v.z), "f"(v.w)
                 : "memory");
    if ((t & 15) == 0) atomicAdd(&g_cnt[b], 1.0f);
}

// ---------------- final FC: out[g] = dot(pool[g], Wfc)/max(cnt,1) + bfc -----
__global__ void k_final(const float* __restrict__ Wfc,
                        const float* __restrict__ bfc,
                        float* __restrict__ out) {
    int g = threadIdx.x;            // 256 threads, 1 block
    float cnt = fmaxf(g_cnt[g], 1.0f);
    float acc = 0.f;
#pragma unroll
    for (int c = 0; c < HID; c++)
        acc += g_pool[g * HID + c] * Wfc[c];
    out[g] = acc / cnt + bfc[0];
}

// ---------------------------------------------------------------------------
extern "C" void kernel_launch(void* const* d_in, const int* in_sizes, int n_in,
                              void* d_out, int out_size) {
    const float* x     = (const float*)d_in[0];
    const int*   ei    = (const int*)  d_in[1];
    const int*   batch = (const int*)  d_in[2];
    const float* W1    = (const float*)d_in[3];
    const float* b1    = (const float*)d_in[4];
    const float* W2    = (const float*)d_in[5];
    const float* b2    = (const float*)d_in[6];
    const float* Wfc   = (const float*)d_in[7];
    const float* bfc   = (const float*)d_in[8];
    float* out = (float*)d_out;

    int n = in_sizes[2];            // nodes (batch vector length)
    int E = in_sizes[1] / 2;        // edges
    const int* src = ei;
    const int* dst = ei + E;

    const int T = 256;
    int gb_n   = (n + T - 1) / T;
    int gb_e   = (E + T - 1) / T;
    int gb_n16 = (n * 16 + T - 1) / T;
    int gb_e16 = (E * 16 + T - 1) / T;
    int gb_m   = (n + 127) / 128;

    // degrees / normalization
    k_init <<<gb_n, T>>>(n);
    k_deg  <<<gb_e, T>>>(dst, E);
    k_dinv <<<gb_n, T>>>(n);

    // layer 1
    k_gemm<512, false><<<gb_m, T>>>(x, W1, n);      // g_h = x @ W1
    k_self <<<gb_n16, T>>>(b1, n);                  // g_o = b1 + g_h*dinv^2
    k_edge <<<gb_e16, T>>>(src, dst, E);            // g_o += scatter(g_h)

    // layer 2 (relu fused into GEMM A-load)
    k_gemm<64, true><<<gb_m, T>>>(nullptr, W2, n);  // g_h = relu(g_o) @ W2
    k_self <<<gb_n16, T>>>(b2, n);                  // g_o = b2 + g_h*dinv^2
    k_edge <<<gb_e16, T>>>(src, dst, E);            // g_o += scatter(g_h)

    // pooling + FC (relu fused into pooling read)
    k_pool <<<gb_n16, T>>>(batch, n);
    k_final<<<1, T>>>(Wfc, bfc, out);
}